// round 1
// baseline (speedup 1.0000x reference)
#include <cuda_runtime.h>
#include <math.h>

#define NN   50000
#define EE   500000
#define KIN  512
#define HH   4
#define CC   64
#define HC   256
#define ET   (EE + NN)

#define NEG_SLOPE 0.2f

// ---------------- scratch (no allocations allowed) ----------------
__device__ float g_h[NN * HC];          // projected features  [N, H*C]
__device__ float g_asrc[NN * HH];       // per-node src attn scores [N, H]
__device__ float g_adst[NN * HH];       // per-node dst attn scores [N, H]
__device__ int   g_deg[NN];             // in-degree (incl. self loop)
__device__ int   g_off[NN + 1];         // CSR offsets
__device__ int   g_cur[NN];             // scatter cursors
__device__ int   g_srcid[ET];           // CSR: source node per incoming edge

// ---------------- 1) GEMM: g_h = x @ W  (fp32, 128x64x16 tiles) ----------------
#define BM 128
#define BN 64
#define BK 16
#define LDA (BM + 4)    // 132 floats; 132*4=528 bytes, 16B-multiple -> float4 reads stay aligned

__global__ __launch_bounds__(256) void gemm_kernel(const float* __restrict__ A,
                                                   const float* __restrict__ B) {
    __shared__ float As[BK * LDA];
    __shared__ float Bs[BK * BN];

    const int tid = threadIdx.x;
    const int m0  = blockIdx.y * BM;
    const int n0  = blockIdx.x * BN;
    const int tx  = tid & 15;     // output col group (4 cols)
    const int ty  = tid >> 4;     // output row group (8 rows)

    float acc[8][4];
#pragma unroll
    for (int r = 0; r < 8; r++)
#pragma unroll
        for (int c = 0; c < 4; c++) acc[r][c] = 0.0f;

    for (int k0 = 0; k0 < KIN; k0 += BK) {
        // Load A tile 128x16 (transposed into As[k][m]); 2 float4 per thread
#pragma unroll
        for (int i = 0; i < 2; i++) {
            int idx = tid * 2 + i;         // 0..511 float4 slots
            int row = idx >> 2;            // 0..127
            int q   = idx & 3;             // 0..3 (k quad)
            int m   = m0 + row;
            float4 v = make_float4(0.f, 0.f, 0.f, 0.f);
            if (m < NN)
                v = *(const float4*)(A + m * KIN + k0 + q * 4);
            As[(q * 4 + 0) * LDA + row] = v.x;
            As[(q * 4 + 1) * LDA + row] = v.y;
            As[(q * 4 + 2) * LDA + row] = v.z;
            As[(q * 4 + 3) * LDA + row] = v.w;
        }
        // Load B tile 16x64; 1 float4 per thread
        {
            int row = tid >> 4;            // 0..15
            int c4  = tid & 15;            // 0..15
            float4 v = *(const float4*)(B + (k0 + row) * HC + n0 + c4 * 4);
            *(float4*)(Bs + row * BN + c4 * 4) = v;
        }
        __syncthreads();

#pragma unroll
        for (int kk = 0; kk < BK; kk++) {
            float ar[8];
            *(float4*)(&ar[0]) = *(const float4*)(As + kk * LDA + ty * 8);
            *(float4*)(&ar[4]) = *(const float4*)(As + kk * LDA + ty * 8 + 4);
            float br[4];
            *(float4*)(&br[0]) = *(const float4*)(Bs + kk * BN + tx * 4);
#pragma unroll
            for (int r = 0; r < 8; r++)
#pragma unroll
                for (int c = 0; c < 4; c++)
                    acc[r][c] = fmaf(ar[r], br[c], acc[r][c]);
        }
        __syncthreads();
    }

#pragma unroll
    for (int r = 0; r < 8; r++) {
        int m = m0 + ty * 8 + r;
        if (m < NN) {
            float4 v = make_float4(acc[r][0], acc[r][1], acc[r][2], acc[r][3]);
            *(float4*)(g_h + m * HC + n0 + tx * 4) = v;
        }
    }
}

// ---------------- 2) attention scalars: a_src/a_dst per (node, head) ----------------
__global__ __launch_bounds__(256) void attn_kernel(const float* __restrict__ att_src,
                                                   const float* __restrict__ att_dst) {
    int warp = (blockIdx.x * blockDim.x + threadIdx.x) >> 5;
    int lane = threadIdx.x & 31;
    if (warp >= NN) return;

    const float4* hr = (const float4*)g_h + warp * (HC / 4);
    float4 v0 = hr[lane * 2];
    float4 v1 = hr[lane * 2 + 1];
    const float4* as4 = (const float4*)att_src;
    const float4* ad4 = (const float4*)att_dst;
    float4 s0 = as4[lane * 2], s1 = as4[lane * 2 + 1];
    float4 d0 = ad4[lane * 2], d1 = ad4[lane * 2 + 1];

    float ss = v0.x * s0.x + v0.y * s0.y + v0.z * s0.z + v0.w * s0.w
             + v1.x * s1.x + v1.y * s1.y + v1.z * s1.z + v1.w * s1.w;
    float sd = v0.x * d0.x + v0.y * d0.y + v0.z * d0.z + v0.w * d0.w
             + v1.x * d1.x + v1.y * d1.y + v1.z * d1.z + v1.w * d1.w;

    // reduce within 8-lane groups (one head per group)
#pragma unroll
    for (int o = 4; o > 0; o >>= 1) {
        ss += __shfl_xor_sync(0xffffffffu, ss, o);
        sd += __shfl_xor_sync(0xffffffffu, sd, o);
    }
    if ((lane & 7) == 0) {
        g_asrc[warp * HH + (lane >> 3)] = ss;
        g_adst[warp * HH + (lane >> 3)] = sd;
    }
}

// ---------------- 3) CSR build ----------------
__global__ void deg_init_kernel() {
    int i = blockIdx.x * blockDim.x + threadIdx.x;
    if (i < NN) g_deg[i] = 1;   // self loop
}

__global__ void deg_count_kernel(const int* __restrict__ ei) {
    int e = blockIdx.x * blockDim.x + threadIdx.x;
    if (e < EE) atomicAdd(&g_deg[ei[EE + e]], 1);
}

__global__ __launch_bounds__(1024) void scan_kernel() {
    __shared__ int wsum[32];
    __shared__ int s_carry;
    __shared__ int s_total;
    const int tid = threadIdx.x, lane = tid & 31, wid = tid >> 5;
    if (tid == 0) s_carry = 0;
    __syncthreads();

    for (int base = 0; base < NN; base += 1024) {
        int i = base + tid;
        int v = (i < NN) ? g_deg[i] : 0;
        int x = v;
#pragma unroll
        for (int o = 1; o < 32; o <<= 1) {
            int y = __shfl_up_sync(0xffffffffu, x, o);
            if (lane >= o) x += y;
        }
        if (lane == 31) wsum[wid] = x;
        __syncthreads();
        if (wid == 0) {
            int w = wsum[lane];
            int xs = w;
#pragma unroll
            for (int o = 1; o < 32; o <<= 1) {
                int y = __shfl_up_sync(0xffffffffu, xs, o);
                if (lane >= o) xs += y;
            }
            wsum[lane] = xs - w;        // exclusive warp-prefix
            if (lane == 31) s_total = xs;
        }
        __syncthreads();
        int incl = x + wsum[wid];
        int off  = s_carry + incl - v;
        if (i < NN) {
            g_off[i]    = off;
            g_srcid[off] = i;           // self loop at segment start
            g_cur[i]    = off + 1;
        }
        __syncthreads();
        if (tid == 0) s_carry += s_total;
        __syncthreads();
    }
    if (tid == 0) g_off[NN] = s_carry;
}

__global__ void scatter_kernel(const int* __restrict__ ei) {
    int e = blockIdx.x * blockDim.x + threadIdx.x;
    if (e < EE) {
        int d = ei[EE + e];
        int p = atomicAdd(&g_cur[d], 1);
        g_srcid[p] = ei[e];
    }
}

// ---------------- 4) softmax + weighted aggregation, one warp per node ----------------
__device__ __forceinline__ float lrelu(float x) { return x >= 0.f ? x : NEG_SLOPE * x; }

__global__ __launch_bounds__(256) void agg_kernel(const float* __restrict__ bias,
                                                  const float* __restrict__ prelu_a,
                                                  float* __restrict__ out) {
    int warp = (blockIdx.x * 256 + threadIdx.x) >> 5;
    int lane = threadIdx.x & 31;
    if (warp >= NN) return;
    const int node = warp;
    const int beg = g_off[node], end = g_off[node + 1];
    const int head = lane >> 3;

    float ad0 = g_adst[node * HH + 0];
    float ad1 = g_adst[node * HH + 1];
    float ad2 = g_adst[node * HH + 2];
    float ad3 = g_adst[node * HH + 3];

    // pass 1: per-head max
    float m0 = -1e30f, m1 = -1e30f, m2 = -1e30f, m3 = -1e30f;
    for (int i = beg + lane; i < end; i += 32) {
        int s = __ldg(&g_srcid[i]);
        float4 a = *(const float4*)(g_asrc + s * HH);
        m0 = fmaxf(m0, lrelu(a.x + ad0));
        m1 = fmaxf(m1, lrelu(a.y + ad1));
        m2 = fmaxf(m2, lrelu(a.z + ad2));
        m3 = fmaxf(m3, lrelu(a.w + ad3));
    }
#pragma unroll
    for (int o = 16; o > 0; o >>= 1) {
        m0 = fmaxf(m0, __shfl_xor_sync(0xffffffffu, m0, o));
        m1 = fmaxf(m1, __shfl_xor_sync(0xffffffffu, m1, o));
        m2 = fmaxf(m2, __shfl_xor_sync(0xffffffffu, m2, o));
        m3 = fmaxf(m3, __shfl_xor_sync(0xffffffffu, m3, o));
    }

    // pass 2: per-head sum of exp
    float s0 = 0.f, s1 = 0.f, s2 = 0.f, s3 = 0.f;
    for (int i = beg + lane; i < end; i += 32) {
        int s = __ldg(&g_srcid[i]);
        float4 a = *(const float4*)(g_asrc + s * HH);
        s0 += __expf(lrelu(a.x + ad0) - m0);
        s1 += __expf(lrelu(a.y + ad1) - m1);
        s2 += __expf(lrelu(a.z + ad2) - m2);
        s3 += __expf(lrelu(a.w + ad3) - m3);
    }
#pragma unroll
    for (int o = 16; o > 0; o >>= 1) {
        s0 += __shfl_xor_sync(0xffffffffu, s0, o);
        s1 += __shfl_xor_sync(0xffffffffu, s1, o);
        s2 += __shfl_xor_sync(0xffffffffu, s2, o);
        s3 += __shfl_xor_sync(0xffffffffu, s3, o);
    }
    float inv0 = 1.f / (s0 + 1e-16f);
    float inv1 = 1.f / (s1 + 1e-16f);
    float inv2 = 1.f / (s2 + 1e-16f);
    float inv3 = 1.f / (s3 + 1e-16f);

    float adh  = (head == 0) ? ad0 : (head == 1) ? ad1 : (head == 2) ? ad2 : ad3;
    float mh   = (head == 0) ? m0  : (head == 1) ? m1  : (head == 2) ? m2  : m3;
    float invh = (head == 0) ? inv0: (head == 1) ? inv1: (head == 2) ? inv2: inv3;

    // pass 3: whole warp cooperates on each edge; lane owns 8 channels of one head
    float acc[8];
#pragma unroll
    for (int j = 0; j < 8; j++) acc[j] = 0.f;

    const float4* h4 = (const float4*)g_h;
    for (int i = beg; i < end; i++) {
        int s = __ldg(&g_srcid[i]);
        float as = __ldg(&g_asrc[s * HH + head]);
        float alpha = __expf(lrelu(as + adh) - mh) * invh;
        float4 v0 = h4[s * (HC / 4) + lane * 2];
        float4 v1 = h4[s * (HC / 4) + lane * 2 + 1];
        acc[0] = fmaf(alpha, v0.x, acc[0]);
        acc[1] = fmaf(alpha, v0.y, acc[1]);
        acc[2] = fmaf(alpha, v0.z, acc[2]);
        acc[3] = fmaf(alpha, v0.w, acc[3]);
        acc[4] = fmaf(alpha, v1.x, acc[4]);
        acc[5] = fmaf(alpha, v1.y, acc[5]);
        acc[6] = fmaf(alpha, v1.z, acc[6]);
        acc[7] = fmaf(alpha, v1.w, acc[7]);
    }

    // epilogue: bias + PReLU
    const float4* b4 = (const float4*)bias;
    float4 b0 = b4[lane * 2], b1 = b4[lane * 2 + 1];
    float pa = prelu_a[0];

    float o0 = acc[0] + b0.x; o0 = o0 >= 0.f ? o0 : pa * o0;
    float o1 = acc[1] + b0.y; o1 = o1 >= 0.f ? o1 : pa * o1;
    float o2 = acc[2] + b0.z; o2 = o2 >= 0.f ? o2 : pa * o2;
    float o3 = acc[3] + b0.w; o3 = o3 >= 0.f ? o3 : pa * o3;
    float o4 = acc[4] + b1.x; o4 = o4 >= 0.f ? o4 : pa * o4;
    float o5 = acc[5] + b1.y; o5 = o5 >= 0.f ? o5 : pa * o5;
    float o6 = acc[6] + b1.z; o6 = o6 >= 0.f ? o6 : pa * o6;
    float o7 = acc[7] + b1.w; o7 = o7 >= 0.f ? o7 : pa * o7;

    float4* out4 = (float4*)out;
    out4[node * (HC / 4) + lane * 2]     = make_float4(o0, o1, o2, o3);
    out4[node * (HC / 4) + lane * 2 + 1] = make_float4(o4, o5, o6, o7);
}

// ---------------- launch ----------------
extern "C" void kernel_launch(void* const* d_in, const int* in_sizes, int n_in,
                              void* d_out, int out_size) {
    const float* x       = (const float*)d_in[0];
    const int*   ei      = (const int*)d_in[1];
    const float* W       = (const float*)d_in[2];
    const float* att_src = (const float*)d_in[3];
    const float* att_dst = (const float*)d_in[4];
    const float* bias    = (const float*)d_in[5];
    const float* prelu_a = (const float*)d_in[6];
    float* out = (float*)d_out;

    dim3 ggrid(HC / BN, (NN + BM - 1) / BM);
    gemm_kernel<<<ggrid, 256>>>(x, W);

    attn_kernel<<<(NN * 32 + 255) / 256, 256>>>(att_src, att_dst);

    deg_init_kernel<<<(NN + 255) / 256, 256>>>();
    deg_count_kernel<<<(EE + 255) / 256, 256>>>(ei);
    scan_kernel<<<1, 1024>>>();
    scatter_kernel<<<(EE + 255) / 256, 256>>>(ei);

    agg_kernel<<<(NN * 32 + 255) / 256, 256>>>(bias, prelu_a, out);
}

// round 3
// speedup vs baseline: 1.7190x; 1.7190x over previous
#include <cuda_runtime.h>
#include <cstdint>
#include <math.h>

#define NN   50000
#define EE   500000
#define KIN  512
#define HH   4
#define CC   64
#define HC   256
#define ET   (EE + NN)

#define NEG_SLOPE 0.2f

// ---------------- scratch (no allocations allowed) ----------------
__device__ float g_h[NN * HC];          // projected features  [N, H*C]
__device__ float g_Wt[HC * KIN];        // W transposed + tf32-rounded [N=256][K=512]
__device__ float g_asrc[NN * HH];       // per-node src attn scores [N, H]
__device__ float g_adst[NN * HH];       // per-node dst attn scores [N, H]
__device__ int   g_deg[NN];             // in-degree (incl. self loop)
__device__ int   g_off[NN + 1];         // CSR offsets
__device__ int   g_cur[NN];             // scatter cursors
__device__ int   g_srcid[ET];           // CSR: source node per incoming edge

__device__ __forceinline__ uint32_t tf32_rna(float f) {
    uint32_t o;
    asm("cvt.rna.tf32.f32 %0, %1;" : "=r"(o) : "f"(f));
    return o;
}

__device__ __forceinline__ void mma_tf32(float* c, const uint32_t* a, const uint32_t* b) {
    asm volatile(
        "mma.sync.aligned.m16n8k8.row.col.f32.tf32.tf32.f32 "
        "{%0,%1,%2,%3}, {%4,%5,%6,%7}, {%8,%9}, {%0,%1,%2,%3};"
        : "+f"(c[0]), "+f"(c[1]), "+f"(c[2]), "+f"(c[3])
        : "r"(a[0]), "r"(a[1]), "r"(a[2]), "r"(a[3]), "r"(b[0]), "r"(b[1]));
}

// ---------------- 0) W transpose + tf32 rounding: g_Wt[n][k] = rna(W[k][n]) ----------------
__global__ void wt_kernel(const float* __restrict__ W) {
    int idx = blockIdx.x * blockDim.x + threadIdx.x;
    if (idx < KIN * HC) {
        int k = idx >> 8;
        int n = idx & 255;
        uint32_t r = tf32_rna(W[idx]);
        *(uint32_t*)&g_Wt[n * KIN + k] = r;
    }
}

// ---------------- 1) GEMM: g_h = x @ W  (mma.sync tf32, 128x128x16 tiles) ----------------
// SMEM rows padded to 20 floats (80 B, 16B-aligned) -> fragment reads bank-conflict-free.
#define BK 16
#define LDS_STRIDE 20

__global__ __launch_bounds__(256, 2) void mma_gemm_kernel(const float* __restrict__ x) {
    __shared__ float As[2][128 * LDS_STRIDE];
    __shared__ float Bs[2][128 * LDS_STRIDE];

    const int tid  = threadIdx.x;
    const int lane = tid & 31;
    const int wid  = tid >> 5;
    const int wm   = wid & 3;       // warp M position (32 rows each)
    const int wn   = wid >> 2;      // warp N position (64 cols each)
    const int m0   = blockIdx.x * 128;
    const int n0   = blockIdx.y * 128;
    const int r4   = lane >> 2;     // fragment row within tile
    const int c4   = lane & 3;      // fragment col within k-panel

    float acc[2][8][4];
#pragma unroll
    for (int mi = 0; mi < 2; mi++)
#pragma unroll
        for (int ni = 0; ni < 8; ni++)
#pragma unroll
            for (int j = 0; j < 4; j++) acc[mi][ni][j] = 0.f;

    float4 pa[2], pb[2];
    int arow[2], aq[2];

    // ---- prefetch stage 0 ----
#pragma unroll
    for (int i = 0; i < 2; i++) {
        int idx = i * 256 + tid;
        int row = idx >> 2, q = idx & 3;
        arow[i] = row; aq[i] = q;
        pa[i] = (m0 + row < NN) ? *(const float4*)(x + (size_t)(m0 + row) * KIN + q * 4)
                                : make_float4(0.f, 0.f, 0.f, 0.f);
        pb[i] = *(const float4*)(g_Wt + (size_t)(n0 + row) * KIN + q * 4);
    }
    // store stage 0
#pragma unroll
    for (int i = 0; i < 2; i++) {
        uint4 va = make_uint4(tf32_rna(pa[i].x), tf32_rna(pa[i].y), tf32_rna(pa[i].z), tf32_rna(pa[i].w));
        *(uint4*)&As[0][arow[i] * LDS_STRIDE + aq[i] * 4] = va;
        uint4 vb = make_uint4(__float_as_uint(pb[i].x), __float_as_uint(pb[i].y),
                              __float_as_uint(pb[i].z), __float_as_uint(pb[i].w));
        *(uint4*)&Bs[0][arow[i] * LDS_STRIDE + aq[i] * 4] = vb;
    }
    __syncthreads();

#pragma unroll 1
    for (int ks = 0; ks < KIN / BK; ks++) {
        const int cur = ks & 1;
        // prefetch next stage
        if (ks < KIN / BK - 1) {
            int kb = (ks + 1) * BK;
#pragma unroll
            for (int i = 0; i < 2; i++) {
                int row = arow[i], q = aq[i];
                pa[i] = (m0 + row < NN) ? *(const float4*)(x + (size_t)(m0 + row) * KIN + kb + q * 4)
                                        : make_float4(0.f, 0.f, 0.f, 0.f);
                pb[i] = *(const float4*)(g_Wt + (size_t)(n0 + row) * KIN + kb + q * 4);
            }
        }

        // compute on current buffer
        const uint32_t* asb = (const uint32_t*)As[cur];
        const uint32_t* bsb = (const uint32_t*)Bs[cur];
#pragma unroll
        for (int kp = 0; kp < 2; kp++) {
            uint32_t afr[2][4];
#pragma unroll
            for (int mi = 0; mi < 2; mi++) {
                int m = wm * 32 + mi * 16 + r4;
                afr[mi][0] = asb[m * LDS_STRIDE + kp * 8 + c4];
                afr[mi][1] = asb[(m + 8) * LDS_STRIDE + kp * 8 + c4];
                afr[mi][2] = asb[m * LDS_STRIDE + kp * 8 + c4 + 4];
                afr[mi][3] = asb[(m + 8) * LDS_STRIDE + kp * 8 + c4 + 4];
            }
            uint32_t bfr[8][2];
#pragma unroll
            for (int ni = 0; ni < 8; ni++) {
                int n = wn * 64 + ni * 8 + r4;
                bfr[ni][0] = bsb[n * LDS_STRIDE + kp * 8 + c4];
                bfr[ni][1] = bsb[n * LDS_STRIDE + kp * 8 + c4 + 4];
            }
#pragma unroll
            for (int mi = 0; mi < 2; mi++)
#pragma unroll
                for (int ni = 0; ni < 8; ni++)
                    mma_tf32(acc[mi][ni], afr[mi], bfr[ni]);
        }

        // store next stage, then sync
        if (ks < KIN / BK - 1) {
            int nxt = (ks + 1) & 1;
#pragma unroll
            for (int i = 0; i < 2; i++) {
                uint4 va = make_uint4(tf32_rna(pa[i].x), tf32_rna(pa[i].y), tf32_rna(pa[i].z), tf32_rna(pa[i].w));
                *(uint4*)&As[nxt][arow[i] * LDS_STRIDE + aq[i] * 4] = va;
                uint4 vb = make_uint4(__float_as_uint(pb[i].x), __float_as_uint(pb[i].y),
                                      __float_as_uint(pb[i].z), __float_as_uint(pb[i].w));
                *(uint4*)&Bs[nxt][arow[i] * LDS_STRIDE + aq[i] * 4] = vb;
            }
            __syncthreads();
        }
    }

    // ---- epilogue: write accumulators ----
#pragma unroll
    for (int mi = 0; mi < 2; mi++) {
#pragma unroll
        for (int ni = 0; ni < 8; ni++) {
            int gm = m0 + wm * 32 + mi * 16 + r4;
            int gn = n0 + wn * 64 + ni * 8 + (c4 << 1);
            if (gm < NN)
                *(float2*)&g_h[(size_t)gm * HC + gn] = make_float2(acc[mi][ni][0], acc[mi][ni][1]);
            if (gm + 8 < NN)
                *(float2*)&g_h[(size_t)(gm + 8) * HC + gn] = make_float2(acc[mi][ni][2], acc[mi][ni][3]);
        }
    }
}

// ---------------- 2) attention scalars: a_src/a_dst per (node, head) ----------------
__global__ __launch_bounds__(256) void attn_kernel(const float* __restrict__ att_src,
                                                   const float* __restrict__ att_dst) {
    int warp = (blockIdx.x * blockDim.x + threadIdx.x) >> 5;
    int lane = threadIdx.x & 31;
    if (warp >= NN) return;

    const float4* hr = (const float4*)g_h + warp * (HC / 4);
    float4 v0 = hr[lane * 2];
    float4 v1 = hr[lane * 2 + 1];
    const float4* as4 = (const float4*)att_src;
    const float4* ad4 = (const float4*)att_dst;
    float4 s0 = as4[lane * 2], s1 = as4[lane * 2 + 1];
    float4 d0 = ad4[lane * 2], d1 = ad4[lane * 2 + 1];

    float ss = v0.x * s0.x + v0.y * s0.y + v0.z * s0.z + v0.w * s0.w
             + v1.x * s1.x + v1.y * s1.y + v1.z * s1.z + v1.w * s1.w;
    float sd = v0.x * d0.x + v0.y * d0.y + v0.z * d0.z + v0.w * d0.w
             + v1.x * d1.x + v1.y * d1.y + v1.z * d1.z + v1.w * d1.w;

#pragma unroll
    for (int o = 4; o > 0; o >>= 1) {
        ss += __shfl_xor_sync(0xffffffffu, ss, o);
        sd += __shfl_xor_sync(0xffffffffu, sd, o);
    }
    if ((lane & 7) == 0) {
        g_asrc[warp * HH + (lane >> 3)] = ss;
        g_adst[warp * HH + (lane >> 3)] = sd;
    }
}

// ---------------- 3) CSR build ----------------
__global__ void deg_init_kernel() {
    int i = blockIdx.x * blockDim.x + threadIdx.x;
    if (i < NN) g_deg[i] = 1;   // self loop
}

__global__ void deg_count_kernel(const int* __restrict__ ei) {
    int e = blockIdx.x * blockDim.x + threadIdx.x;
    if (e < EE) atomicAdd(&g_deg[ei[EE + e]], 1);
}

__global__ __launch_bounds__(1024) void scan_kernel() {
    __shared__ int wsum[32];
    __shared__ int s_carry;
    __shared__ int s_total;
    const int tid = threadIdx.x, lane = tid & 31, wid = tid >> 5;
    if (tid == 0) s_carry = 0;
    __syncthreads();

    for (int base = 0; base < NN; base += 1024) {
        int i = base + tid;
        int v = (i < NN) ? g_deg[i] : 0;
        int x = v;
#pragma unroll
        for (int o = 1; o < 32; o <<= 1) {
            int y = __shfl_up_sync(0xffffffffu, x, o);
            if (lane >= o) x += y;
        }
        if (lane == 31) wsum[wid] = x;
        __syncthreads();
        if (wid == 0) {
            int w = wsum[lane];
            int xs = w;
#pragma unroll
            for (int o = 1; o < 32; o <<= 1) {
                int y = __shfl_up_sync(0xffffffffu, xs, o);
                if (lane >= o) xs += y;
            }
            wsum[lane] = xs - w;
            if (lane == 31) s_total = xs;
        }
        __syncthreads();
        int incl = x + wsum[wid];
        int off  = s_carry + incl - v;
        if (i < NN) {
            g_off[i]    = off;
            g_srcid[off] = i;           // self loop at segment start
            g_cur[i]    = off + 1;
        }
        __syncthreads();
        if (tid == 0) s_carry += s_total;
        __syncthreads();
    }
    if (tid == 0) g_off[NN] = s_carry;
}

__global__ void scatter_kernel(const int* __restrict__ ei) {
    int e = blockIdx.x * blockDim.x + threadIdx.x;
    if (e < EE) {
        int d = ei[EE + e];
        int p = atomicAdd(&g_cur[d], 1);
        g_srcid[p] = ei[e];
    }
}

// ---------------- 4) softmax + weighted aggregation, one warp per node ----------------
__device__ __forceinline__ float lrelu(float x) { return x >= 0.f ? x : NEG_SLOPE * x; }

__global__ __launch_bounds__(256) void agg_kernel(const float* __restrict__ bias,
                                                  const float* __restrict__ prelu_a,
                                                  float* __restrict__ out) {
    int warp = (blockIdx.x * 256 + threadIdx.x) >> 5;
    int lane = threadIdx.x & 31;
    if (warp >= NN) return;
    const int node = warp;
    const int beg = g_off[node], end = g_off[node + 1];
    const int head = lane >> 3;

    float ad0 = g_adst[node * HH + 0];
    float ad1 = g_adst[node * HH + 1];
    float ad2 = g_adst[node * HH + 2];
    float ad3 = g_adst[node * HH + 3];

    float m0 = -1e30f, m1 = -1e30f, m2 = -1e30f, m3 = -1e30f;
    for (int i = beg + lane; i < end; i += 32) {
        int s = __ldg(&g_srcid[i]);
        float4 a = *(const float4*)(g_asrc + s * HH);
        m0 = fmaxf(m0, lrelu(a.x + ad0));
        m1 = fmaxf(m1, lrelu(a.y + ad1));
        m2 = fmaxf(m2, lrelu(a.z + ad2));
        m3 = fmaxf(m3, lrelu(a.w + ad3));
    }
#pragma unroll
    for (int o = 16; o > 0; o >>= 1) {
        m0 = fmaxf(m0, __shfl_xor_sync(0xffffffffu, m0, o));
        m1 = fmaxf(m1, __shfl_xor_sync(0xffffffffu, m1, o));
        m2 = fmaxf(m2, __shfl_xor_sync(0xffffffffu, m2, o));
        m3 = fmaxf(m3, __shfl_xor_sync(0xffffffffu, m3, o));
    }

    float s0 = 0.f, s1 = 0.f, s2 = 0.f, s3 = 0.f;
    for (int i = beg + lane; i < end; i += 32) {
        int s = __ldg(&g_srcid[i]);
        float4 a = *(const float4*)(g_asrc + s * HH);
        s0 += __expf(lrelu(a.x + ad0) - m0);
        s1 += __expf(lrelu(a.y + ad1) - m1);
        s2 += __expf(lrelu(a.z + ad2) - m2);
        s3 += __expf(lrelu(a.w + ad3) - m3);
    }
#pragma unroll
    for (int o = 16; o > 0; o >>= 1) {
        s0 += __shfl_xor_sync(0xffffffffu, s0, o);
        s1 += __shfl_xor_sync(0xffffffffu, s1, o);
        s2 += __shfl_xor_sync(0xffffffffu, s2, o);
        s3 += __shfl_xor_sync(0xffffffffu, s3, o);
    }
    float inv0 = 1.f / (s0 + 1e-16f);
    float inv1 = 1.f / (s1 + 1e-16f);
    float inv2 = 1.f / (s2 + 1e-16f);
    float inv3 = 1.f / (s3 + 1e-16f);

    float adh  = (head == 0) ? ad0 : (head == 1) ? ad1 : (head == 2) ? ad2 : ad3;
    float mh   = (head == 0) ? m0  : (head == 1) ? m1  : (head == 2) ? m2  : m3;
    float invh = (head == 0) ? inv0: (head == 1) ? inv1: (head == 2) ? inv2: inv3;

    float acc[8];
#pragma unroll
    for (int j = 0; j < 8; j++) acc[j] = 0.f;

    const float4* h4 = (const float4*)g_h;
    for (int i = beg; i < end; i++) {
        int s = __ldg(&g_srcid[i]);
        float as = __ldg(&g_asrc[s * HH + head]);
        float alpha = __expf(lrelu(as + adh) - mh) * invh;
        float4 v0 = h4[s * (HC / 4) + lane * 2];
        float4 v1 = h4[s * (HC / 4) + lane * 2 + 1];
        acc[0] = fmaf(alpha, v0.x, acc[0]);
        acc[1] = fmaf(alpha, v0.y, acc[1]);
        acc[2] = fmaf(alpha, v0.z, acc[2]);
        acc[3] = fmaf(alpha, v0.w, acc[3]);
        acc[4] = fmaf(alpha, v1.x, acc[4]);
        acc[5] = fmaf(alpha, v1.y, acc[5]);
        acc[6] = fmaf(alpha, v1.z, acc[6]);
        acc[7] = fmaf(alpha, v1.w, acc[7]);
    }

    const float4* b4 = (const float4*)bias;
    float4 b0 = b4[lane * 2], b1 = b4[lane * 2 + 1];
    float pa = prelu_a[0];

    float o0 = acc[0] + b0.x; o0 = o0 >= 0.f ? o0 : pa * o0;
    float o1 = acc[1] + b0.y; o1 = o1 >= 0.f ? o1 : pa * o1;
    float o2 = acc[2] + b0.z; o2 = o2 >= 0.f ? o2 : pa * o2;
    float o3 = acc[3] + b0.w; o3 = o3 >= 0.f ? o3 : pa * o3;
    float o4 = acc[4] + b1.x; o4 = o4 >= 0.f ? o4 : pa * o4;
    float o5 = acc[5] + b1.y; o5 = o5 >= 0.f ? o5 : pa * o5;
    float o6 = acc[6] + b1.z; o6 = o6 >= 0.f ? o6 : pa * o6;
    float o7 = acc[7] + b1.w; o7 = o7 >= 0.f ? o7 : pa * o7;

    float4* out4 = (float4*)out;
    out4[node * (HC / 4) + lane * 2]     = make_float4(o0, o1, o2, o3);
    out4[node * (HC / 4) + lane * 2 + 1] = make_float4(o4, o5, o6, o7);
}

// ---------------- launch ----------------
extern "C" void kernel_launch(void* const* d_in, const int* in_sizes, int n_in,
                              void* d_out, int out_size) {
    const float* x       = (const float*)d_in[0];
    const int*   ei      = (const int*)d_in[1];
    const float* W       = (const float*)d_in[2];
    const float* att_src = (const float*)d_in[3];
    const float* att_dst = (const float*)d_in[4];
    const float* bias    = (const float*)d_in[5];
    const float* prelu_a = (const float*)d_in[6];
    float* out = (float*)d_out;

    wt_kernel<<<(KIN * HC + 255) / 256, 256>>>(W);

    dim3 ggrid((NN + 127) / 128, HC / 128);
    mma_gemm_kernel<<<ggrid, 256>>>(x);

    attn_kernel<<<(NN * 32 + 255) / 256, 256>>>(att_src, att_dst);

    deg_init_kernel<<<(NN + 255) / 256, 256>>>();
    deg_count_kernel<<<(EE + 255) / 256, 256>>>(ei);
    scan_kernel<<<1, 1024>>>();
    scatter_kernel<<<(EE + 255) / 256, 256>>>(ei);

    agg_kernel<<<(NN * 32 + 255) / 256, 256>>>(bias, prelu_a, out);
}

// round 4
// speedup vs baseline: 2.5280x; 1.4706x over previous
#include <cuda_runtime.h>
#include <cstdint>
#include <math.h>

#define NN   50000
#define EE   500000
#define KIN  512
#define HH   4
#define CC   64
#define HC   256
#define ET   (EE + NN)

#define NEG_SLOPE 0.2f

// ---------------- scratch (no allocations allowed) ----------------
__device__ float g_h[NN * HC];          // projected features  [N, H*C]
__device__ float g_Wt[HC * KIN];        // W transposed + tf32-rounded [N=256][K=512]
__device__ float g_asrc[NN * HH];       // per-node src attn scores [N, H]
__device__ float g_adst[NN * HH];       // per-node dst attn scores [N, H]
__device__ int   g_deg[NN];             // in-degree (incl. self loop)
__device__ int   g_off[NN + 1];         // CSR offsets
__device__ int   g_cur[NN];             // scatter cursors
__device__ int   g_srcid[ET];           // CSR: source node per incoming edge

__device__ __forceinline__ uint32_t tf32_rna(float f) {
    uint32_t o;
    asm("cvt.rna.tf32.f32 %0, %1;" : "=r"(o) : "f"(f));
    return o;
}

__device__ __forceinline__ void mma_tf32(float* c, const uint32_t* a, const uint32_t* b) {
    asm volatile(
        "mma.sync.aligned.m16n8k8.row.col.f32.tf32.tf32.f32 "
        "{%0,%1,%2,%3}, {%4,%5,%6,%7}, {%8,%9}, {%0,%1,%2,%3};"
        : "+f"(c[0]), "+f"(c[1]), "+f"(c[2]), "+f"(c[3])
        : "r"(a[0]), "r"(a[1]), "r"(a[2]), "r"(a[3]), "r"(b[0]), "r"(b[1]));
}

__device__ __forceinline__ uint32_t smem_u32(const void* p) {
    uint32_t a;
    asm("{ .reg .u64 t; cvta.to.shared.u64 t, %1; cvt.u32.u64 %0, t; }" : "=r"(a) : "l"(p));
    return a;
}
__device__ __forceinline__ void cp_async16(uint32_t dst, const void* src, int sz) {
    asm volatile("cp.async.cg.shared.global [%0], [%1], 16, %2;"
                 :: "r"(dst), "l"(src), "r"(sz) : "memory");
}
#define CP_COMMIT() asm volatile("cp.async.commit_group;" ::: "memory")
#define CP_WAIT2()  asm volatile("cp.async.wait_group 2;" ::: "memory")

// ---------------- 0) W transpose + tf32 rounding: g_Wt[n][k] = rna(W[k][n]) ----------------
__global__ void wt_kernel(const float* __restrict__ W) {
    int idx = blockIdx.x * blockDim.x + threadIdx.x;
    if (idx < KIN * HC) {
        int k = idx >> 8;
        int n = idx & 255;
        uint32_t r = tf32_rna(W[idx]);
        *(uint32_t*)&g_Wt[n * KIN + k] = r;
    }
}

// ---------------- 1) GEMM + fused attn scalars (mma.sync tf32, cp.async 4-stage) ----------------
#define BK 16
#define NSTAGE 4
#define LDS_STRIDE 20
#define A_OFF 0
#define B_OFF 10240
#define STG_BYTES 20480
#define GEMM_SMEM (NSTAGE * STG_BYTES)
#define NKS (KIN / BK)   // 32

__global__ __launch_bounds__(256, 2) void mma_gemm_kernel(const float* __restrict__ x,
                                                          const float* __restrict__ att_src,
                                                          const float* __restrict__ att_dst) {
    extern __shared__ char smem[];
    const uint32_t sb = smem_u32(smem);

    const int tid  = threadIdx.x;
    const int lane = tid & 31;
    const int wid  = tid >> 5;
    const int wm   = wid & 3;       // warp M position (32 rows each)
    const int wn   = wid >> 2;      // warp N position (64 cols each)
    const int n0   = blockIdx.x * 128;
    const int m0   = blockIdx.y * 128;
    const int head = blockIdx.x * 2 + wn;   // each warp's 64 cols = one head
    const int r4   = lane >> 2;
    const int c4   = lane & 3;

    // per-thread cp.async chunk coords (2 chunks for A, 2 for B)
    const int rowc0 = tid >> 2,         qc0 = tid & 3;
    const int rowc1 = (tid + 256) >> 2, qc1 = (tid + 256) & 3;
    const float* gA0 = x + (size_t)(m0 + rowc0) * KIN + qc0 * 4;
    const float* gA1 = x + (size_t)(m0 + rowc1) * KIN + qc1 * 4;
    const float* gB0 = g_Wt + (size_t)(n0 + rowc0) * KIN + qc0 * 4;
    const float* gB1 = g_Wt + (size_t)(n0 + rowc1) * KIN + qc1 * 4;
    const int szA0 = (m0 + rowc0 < NN) ? 16 : 0;
    const int szA1 = (m0 + rowc1 < NN) ? 16 : 0;
    const uint32_t dA0 = (uint32_t)((rowc0 * LDS_STRIDE + qc0 * 4) * 4);
    const uint32_t dA1 = (uint32_t)((rowc1 * LDS_STRIDE + qc1 * 4) * 4);

    auto issue = [&](int s) {
        uint32_t st = sb + (uint32_t)(s & (NSTAGE - 1)) * STG_BYTES;
        int kb = s * BK;
        cp_async16(st + A_OFF + dA0, gA0 + kb, szA0);
        cp_async16(st + A_OFF + dA1, gA1 + kb, szA1);
        cp_async16(st + B_OFF + dA0, gB0 + kb, 16);
        cp_async16(st + B_OFF + dA1, gB1 + kb, 16);
    };

    float acc[2][8][4];
#pragma unroll
    for (int mi = 0; mi < 2; mi++)
#pragma unroll
        for (int ni = 0; ni < 8; ni++)
#pragma unroll
            for (int j = 0; j < 4; j++) acc[mi][ni][j] = 0.f;

    // prologue: stages 0..2
#pragma unroll
    for (int s = 0; s < NSTAGE - 1; s++) { issue(s); CP_COMMIT(); }

#pragma unroll 1
    for (int ks = 0; ks < NKS; ks++) {
        CP_WAIT2();
        __syncthreads();
        if (ks + NSTAGE - 1 < NKS) issue(ks + NSTAGE - 1);
        CP_COMMIT();

        const uint32_t slot = (uint32_t)(ks & (NSTAGE - 1)) * STG_BYTES;
        const uint32_t* asb = (const uint32_t*)(smem + slot + A_OFF);
        const uint32_t* bsb = (const uint32_t*)(smem + slot + B_OFF);

#pragma unroll
        for (int kp = 0; kp < 2; kp++) {
            uint32_t afr[2][4];
#pragma unroll
            for (int mi = 0; mi < 2; mi++) {
                int m = wm * 32 + mi * 16 + r4;
                uint32_t a0 = asb[m * LDS_STRIDE + kp * 8 + c4];
                uint32_t a1 = asb[(m + 8) * LDS_STRIDE + kp * 8 + c4];
                uint32_t a2 = asb[m * LDS_STRIDE + kp * 8 + c4 + 4];
                uint32_t a3 = asb[(m + 8) * LDS_STRIDE + kp * 8 + c4 + 4];
                afr[mi][0] = tf32_rna(__uint_as_float(a0));
                afr[mi][1] = tf32_rna(__uint_as_float(a1));
                afr[mi][2] = tf32_rna(__uint_as_float(a2));
                afr[mi][3] = tf32_rna(__uint_as_float(a3));
            }
            uint32_t bfr[8][2];
#pragma unroll
            for (int ni = 0; ni < 8; ni++) {
                int n = wn * 64 + ni * 8 + r4;
                bfr[ni][0] = bsb[n * LDS_STRIDE + kp * 8 + c4];
                bfr[ni][1] = bsb[n * LDS_STRIDE + kp * 8 + c4 + 4];
            }
#pragma unroll
            for (int mi = 0; mi < 2; mi++)
#pragma unroll
                for (int ni = 0; ni < 8; ni++)
                    mma_tf32(acc[mi][ni], afr[mi], bfr[ni]);
        }
    }

    // ---- fused attn scalars: per-warp columns = one head ----
    float avs[8][2], avd[8][2];
#pragma unroll
    for (int ni = 0; ni < 8; ni++) {
        int gn = head * 64 + ni * 8 + c4 * 2;
        avs[ni][0] = __ldg(&att_src[gn]);
        avs[ni][1] = __ldg(&att_src[gn + 1]);
        avd[ni][0] = __ldg(&att_dst[gn]);
        avd[ni][1] = __ldg(&att_dst[gn + 1]);
    }
#pragma unroll
    for (int mi = 0; mi < 2; mi++) {
        float ps0 = 0.f, ps1 = 0.f, pd0 = 0.f, pd1 = 0.f;
#pragma unroll
        for (int ni = 0; ni < 8; ni++) {
            ps0 += acc[mi][ni][0] * avs[ni][0] + acc[mi][ni][1] * avs[ni][1];
            ps1 += acc[mi][ni][2] * avs[ni][0] + acc[mi][ni][3] * avs[ni][1];
            pd0 += acc[mi][ni][0] * avd[ni][0] + acc[mi][ni][1] * avd[ni][1];
            pd1 += acc[mi][ni][2] * avd[ni][0] + acc[mi][ni][3] * avd[ni][1];
        }
#pragma unroll
        for (int o = 1; o <= 2; o <<= 1) {
            ps0 += __shfl_xor_sync(0xffffffffu, ps0, o);
            ps1 += __shfl_xor_sync(0xffffffffu, ps1, o);
            pd0 += __shfl_xor_sync(0xffffffffu, pd0, o);
            pd1 += __shfl_xor_sync(0xffffffffu, pd1, o);
        }
        if (c4 == 0) {
            int gmA = m0 + wm * 32 + mi * 16 + r4;
            int gmB = gmA + 8;
            if (gmA < NN) { g_asrc[gmA * HH + head] = ps0; g_adst[gmA * HH + head] = pd0; }
            if (gmB < NN) { g_asrc[gmB * HH + head] = ps1; g_adst[gmB * HH + head] = pd1; }
        }
    }

    // ---- write h ----
#pragma unroll
    for (int mi = 0; mi < 2; mi++) {
#pragma unroll
        for (int ni = 0; ni < 8; ni++) {
            int gm = m0 + wm * 32 + mi * 16 + r4;
            int gn = n0 + wn * 64 + ni * 8 + (c4 << 1);
            if (gm < NN)
                *(float2*)&g_h[(size_t)gm * HC + gn] = make_float2(acc[mi][ni][0], acc[mi][ni][1]);
            if (gm + 8 < NN)
                *(float2*)&g_h[(size_t)(gm + 8) * HC + gn] = make_float2(acc[mi][ni][2], acc[mi][ni][3]);
        }
    }
}

// ---------------- 3) CSR build ----------------
__global__ void deg_init_kernel() {
    int i = blockIdx.x * blockDim.x + threadIdx.x;
    if (i < NN) g_deg[i] = 1;   // self loop
}

__global__ void deg_count_kernel(const int* __restrict__ ei) {
    int e = blockIdx.x * blockDim.x + threadIdx.x;
    if (e < EE) atomicAdd(&g_deg[ei[EE + e]], 1);
}

__global__ __launch_bounds__(1024) void scan_kernel() {
    __shared__ int wsum[32];
    __shared__ int s_carry;
    __shared__ int s_total;
    const int tid = threadIdx.x, lane = tid & 31, wid = tid >> 5;
    if (tid == 0) s_carry = 0;
    __syncthreads();

    for (int base = 0; base < NN; base += 1024) {
        int i = base + tid;
        int v = (i < NN) ? g_deg[i] : 0;
        int x = v;
#pragma unroll
        for (int o = 1; o < 32; o <<= 1) {
            int y = __shfl_up_sync(0xffffffffu, x, o);
            if (lane >= o) x += y;
        }
        if (lane == 31) wsum[wid] = x;
        __syncthreads();
        if (wid == 0) {
            int w = wsum[lane];
            int xs = w;
#pragma unroll
            for (int o = 1; o < 32; o <<= 1) {
                int y = __shfl_up_sync(0xffffffffu, xs, o);
                if (lane >= o) xs += y;
            }
            wsum[lane] = xs - w;
            if (lane == 31) s_total = xs;
        }
        __syncthreads();
        int incl = x + wsum[wid];
        int off  = s_carry + incl - v;
        if (i < NN) {
            g_off[i]    = off;
            g_srcid[off] = i;           // self loop at segment start
            g_cur[i]    = off + 1;
        }
        __syncthreads();
        if (tid == 0) s_carry += s_total;
        __syncthreads();
    }
    if (tid == 0) g_off[NN] = s_carry;
}

__global__ void scatter_kernel(const int* __restrict__ ei) {
    int e = blockIdx.x * blockDim.x + threadIdx.x;
    if (e < EE) {
        int d = ei[EE + e];
        int p = atomicAdd(&g_cur[d], 1);
        g_srcid[p] = ei[e];
    }
}

// ---------------- 4) softmax + weighted aggregation, one warp per node ----------------
__device__ __forceinline__ float lrelu(float x) { return x >= 0.f ? x : NEG_SLOPE * x; }

__global__ __launch_bounds__(256) void agg_kernel(const float* __restrict__ bias,
                                                  const float* __restrict__ prelu_a,
                                                  float* __restrict__ out) {
    int warp = (blockIdx.x * 256 + threadIdx.x) >> 5;
    int lane = threadIdx.x & 31;
    if (warp >= NN) return;
    const int node = warp;
    const int beg = g_off[node], end = g_off[node + 1];
    const int head = lane >> 3;

    float ad0 = g_adst[node * HH + 0];
    float ad1 = g_adst[node * HH + 1];
    float ad2 = g_adst[node * HH + 2];
    float ad3 = g_adst[node * HH + 3];

    float m0 = -1e30f, m1 = -1e30f, m2 = -1e30f, m3 = -1e30f;
    for (int i = beg + lane; i < end; i += 32) {
        int s = __ldg(&g_srcid[i]);
        float4 a = *(const float4*)(g_asrc + s * HH);
        m0 = fmaxf(m0, lrelu(a.x + ad0));
        m1 = fmaxf(m1, lrelu(a.y + ad1));
        m2 = fmaxf(m2, lrelu(a.z + ad2));
        m3 = fmaxf(m3, lrelu(a.w + ad3));
    }
#pragma unroll
    for (int o = 16; o > 0; o >>= 1) {
        m0 = fmaxf(m0, __shfl_xor_sync(0xffffffffu, m0, o));
        m1 = fmaxf(m1, __shfl_xor_sync(0xffffffffu, m1, o));
        m2 = fmaxf(m2, __shfl_xor_sync(0xffffffffu, m2, o));
        m3 = fmaxf(m3, __shfl_xor_sync(0xffffffffu, m3, o));
    }

    float s0 = 0.f, s1 = 0.f, s2 = 0.f, s3 = 0.f;
    for (int i = beg + lane; i < end; i += 32) {
        int s = __ldg(&g_srcid[i]);
        float4 a = *(const float4*)(g_asrc + s * HH);
        s0 += __expf(lrelu(a.x + ad0) - m0);
        s1 += __expf(lrelu(a.y + ad1) - m1);
        s2 += __expf(lrelu(a.z + ad2) - m2);
        s3 += __expf(lrelu(a.w + ad3) - m3);
    }
#pragma unroll
    for (int o = 16; o > 0; o >>= 1) {
        s0 += __shfl_xor_sync(0xffffffffu, s0, o);
        s1 += __shfl_xor_sync(0xffffffffu, s1, o);
        s2 += __shfl_xor_sync(0xffffffffu, s2, o);
        s3 += __shfl_xor_sync(0xffffffffu, s3, o);
    }
    float inv0 = 1.f / (s0 + 1e-16f);
    float inv1 = 1.f / (s1 + 1e-16f);
    float inv2 = 1.f / (s2 + 1e-16f);
    float inv3 = 1.f / (s3 + 1e-16f);

    float adh  = (head == 0) ? ad0 : (head == 1) ? ad1 : (head == 2) ? ad2 : ad3;
    float mh   = (head == 0) ? m0  : (head == 1) ? m1  : (head == 2) ? m2  : m3;
    float invh = (head == 0) ? inv0: (head == 1) ? inv1: (head == 2) ? inv2: inv3;

    float acc[8];
#pragma unroll
    for (int j = 0; j < 8; j++) acc[j] = 0.f;

    const float4* h4 = (const float4*)g_h;
    for (int i = beg; i < end; i++) {
        int s = __ldg(&g_srcid[i]);
        float as = __ldg(&g_asrc[s * HH + head]);
        float alpha = __expf(lrelu(as + adh) - mh) * invh;
        float4 v0 = h4[s * (HC / 4) + lane * 2];
        float4 v1 = h4[s * (HC / 4) + lane * 2 + 1];
        acc[0] = fmaf(alpha, v0.x, acc[0]);
        acc[1] = fmaf(alpha, v0.y, acc[1]);
        acc[2] = fmaf(alpha, v0.z, acc[2]);
        acc[3] = fmaf(alpha, v0.w, acc[3]);
        acc[4] = fmaf(alpha, v1.x, acc[4]);
        acc[5] = fmaf(alpha, v1.y, acc[5]);
        acc[6] = fmaf(alpha, v1.z, acc[6]);
        acc[7] = fmaf(alpha, v1.w, acc[7]);
    }

    const float4* b4 = (const float4*)bias;
    float4 b0 = b4[lane * 2], b1 = b4[lane * 2 + 1];
    float pa = prelu_a[0];

    float o0 = acc[0] + b0.x; o0 = o0 >= 0.f ? o0 : pa * o0;
    float o1 = acc[1] + b0.y; o1 = o1 >= 0.f ? o1 : pa * o1;
    float o2 = acc[2] + b0.z; o2 = o2 >= 0.f ? o2 : pa * o2;
    float o3 = acc[3] + b0.w; o3 = o3 >= 0.f ? o3 : pa * o3;
    float o4 = acc[4] + b1.x; o4 = o4 >= 0.f ? o4 : pa * o4;
    float o5 = acc[5] + b1.y; o5 = o5 >= 0.f ? o5 : pa * o5;
    float o6 = acc[6] + b1.z; o6 = o6 >= 0.f ? o6 : pa * o6;
    float o7 = acc[7] + b1.w; o7 = o7 >= 0.f ? o7 : pa * o7;

    float4* out4 = (float4*)out;
    out4[node * (HC / 4) + lane * 2]     = make_float4(o0, o1, o2, o3);
    out4[node * (HC / 4) + lane * 2 + 1] = make_float4(o4, o5, o6, o7);
}

// ---------------- launch ----------------
extern "C" void kernel_launch(void* const* d_in, const int* in_sizes, int n_in,
                              void* d_out, int out_size) {
    const float* x       = (const float*)d_in[0];
    const int*   ei      = (const int*)d_in[1];
    const float* W       = (const float*)d_in[2];
    const float* att_src = (const float*)d_in[3];
    const float* att_dst = (const float*)d_in[4];
    const float* bias    = (const float*)d_in[5];
    const float* prelu_a = (const float*)d_in[6];
    float* out = (float*)d_out;

    static cudaStream_t s2;
    static cudaEvent_t evf, evj;
    static bool init_done = false;
    if (!init_done) {
        cudaStreamCreateWithFlags(&s2, cudaStreamNonBlocking);
        cudaEventCreateWithFlags(&evf, cudaEventDisableTiming);
        cudaEventCreateWithFlags(&evj, cudaEventDisableTiming);
        cudaFuncSetAttribute(mma_gemm_kernel, cudaFuncAttributeMaxDynamicSharedMemorySize, GEMM_SMEM);
        init_done = true;
    }

    // fork: CSR build on side stream, overlapped with GEMM
    cudaEventRecord(evf, 0);
    cudaStreamWaitEvent(s2, evf, 0);
    deg_init_kernel<<<(NN + 255) / 256, 256, 0, s2>>>();
    deg_count_kernel<<<(EE + 255) / 256, 256, 0, s2>>>(ei);
    scan_kernel<<<1, 1024, 0, s2>>>();
    scatter_kernel<<<(EE + 255) / 256, 256, 0, s2>>>(ei);
    cudaEventRecord(evj, s2);

    // main stream: projection + fused attn scalars
    wt_kernel<<<(KIN * HC + 255) / 256, 256>>>(W);
    dim3 ggrid(2, (NN + 127) / 128);
    mma_gemm_kernel<<<ggrid, 256, GEMM_SMEM>>>(x, att_src, att_dst);

    // join, then aggregate
    cudaStreamWaitEvent(0, evj, 0);
    agg_kernel<<<(NN * 32 + 255) / 256, 256>>>(bias, prelu_a, out);
}

// round 5
// speedup vs baseline: 2.7299x; 1.0798x over previous
#include <cuda_runtime.h>
#include <cuda_fp16.h>
#include <cstdint>
#include <math.h>

#define NN   50000
#define EE   500000
#define KIN  512
#define HH   4
#define CC   64
#define HC   256
#define ET   (EE + NN)

#define NEG_SLOPE 0.2f

// ---------------- scratch (no allocations allowed) ----------------
__device__ __half g_h16[NN * HC];       // projected features, fp16 copy for gather
__device__ float g_Wt[HC * KIN];        // W transposed + tf32-rounded [N=256][K=512]
__device__ float g_asrc[NN * HH];       // per-node src attn scores [N, H]
__device__ float g_adst[NN * HH];       // per-node dst attn scores [N, H]
__device__ float g_expe[ET * HH];       // per-edge-slot exp(e) for 4 heads
__device__ float g_inv[NN * HH];        // per-node 1/denominator
__device__ int   g_deg[NN];             // in-degree (incl. self loop)
__device__ int   g_off[NN + 1];         // CSR offsets
__device__ int   g_cur[NN];             // scatter cursors
__device__ int   g_srcid[ET];           // CSR: source node per incoming edge

__device__ __forceinline__ uint32_t tf32_rna(float f) {
    uint32_t o;
    asm("cvt.rna.tf32.f32 %0, %1;" : "=r"(o) : "f"(f));
    return o;
}

__device__ __forceinline__ void mma_tf32(float* c, const uint32_t* a, const uint32_t* b) {
    asm volatile(
        "mma.sync.aligned.m16n8k8.row.col.f32.tf32.tf32.f32 "
        "{%0,%1,%2,%3}, {%4,%5,%6,%7}, {%8,%9}, {%0,%1,%2,%3};"
        : "+f"(c[0]), "+f"(c[1]), "+f"(c[2]), "+f"(c[3])
        : "r"(a[0]), "r"(a[1]), "r"(a[2]), "r"(a[3]), "r"(b[0]), "r"(b[1]));
}

__device__ __forceinline__ uint32_t smem_u32(const void* p) {
    uint32_t a;
    asm("{ .reg .u64 t; cvta.to.shared.u64 t, %1; cvt.u32.u64 %0, t; }" : "=r"(a) : "l"(p));
    return a;
}
__device__ __forceinline__ void cp_async16(uint32_t dst, const void* src, int sz) {
    asm volatile("cp.async.cg.shared.global [%0], [%1], 16, %2;"
                 :: "r"(dst), "l"(src), "r"(sz) : "memory");
}
#define CP_COMMIT() asm volatile("cp.async.commit_group;" ::: "memory")
#define CP_WAIT2()  asm volatile("cp.async.wait_group 2;" ::: "memory")

// ---------------- 0) W transpose + tf32 rounding ----------------
__global__ void wt_kernel(const float* __restrict__ W) {
    int idx = blockIdx.x * blockDim.x + threadIdx.x;
    if (idx < KIN * HC) {
        int k = idx >> 8;
        int n = idx & 255;
        uint32_t r = tf32_rna(W[idx]);
        *(uint32_t*)&g_Wt[n * KIN + k] = r;
    }
}

// ---------------- 1) GEMM + fused attn scalars (mma.sync tf32, cp.async 4-stage) ----------------
#define BK 16
#define NSTAGE 4
#define LDS_STRIDE 20
#define A_OFF 0
#define B_OFF 10240
#define STG_BYTES 20480
#define GEMM_SMEM (NSTAGE * STG_BYTES)
#define NKS (KIN / BK)   // 32

__global__ __launch_bounds__(256, 2) void mma_gemm_kernel(const float* __restrict__ x,
                                                          const float* __restrict__ att_src,
                                                          const float* __restrict__ att_dst) {
    extern __shared__ char smem[];
    const uint32_t sb = smem_u32(smem);

    const int tid  = threadIdx.x;
    const int lane = tid & 31;
    const int wid  = tid >> 5;
    const int wm   = wid & 3;
    const int wn   = wid >> 2;
    const int n0   = blockIdx.x * 128;
    const int m0   = blockIdx.y * 128;
    const int head = blockIdx.x * 2 + wn;
    const int r4   = lane >> 2;
    const int c4   = lane & 3;

    const int rowc0 = tid >> 2,         qc0 = tid & 3;
    const int rowc1 = (tid + 256) >> 2, qc1 = (tid + 256) & 3;
    const float* gA0 = x + (size_t)(m0 + rowc0) * KIN + qc0 * 4;
    const float* gA1 = x + (size_t)(m0 + rowc1) * KIN + qc1 * 4;
    const float* gB0 = g_Wt + (size_t)(n0 + rowc0) * KIN + qc0 * 4;
    const float* gB1 = g_Wt + (size_t)(n0 + rowc1) * KIN + qc1 * 4;
    const int szA0 = (m0 + rowc0 < NN) ? 16 : 0;
    const int szA1 = (m0 + rowc1 < NN) ? 16 : 0;
    const uint32_t dA0 = (uint32_t)((rowc0 * LDS_STRIDE + qc0 * 4) * 4);
    const uint32_t dA1 = (uint32_t)((rowc1 * LDS_STRIDE + qc1 * 4) * 4);

    auto issue = [&](int s) {
        uint32_t st = sb + (uint32_t)(s & (NSTAGE - 1)) * STG_BYTES;
        int kb = s * BK;
        cp_async16(st + A_OFF + dA0, gA0 + kb, szA0);
        cp_async16(st + A_OFF + dA1, gA1 + kb, szA1);
        cp_async16(st + B_OFF + dA0, gB0 + kb, 16);
        cp_async16(st + B_OFF + dA1, gB1 + kb, 16);
    };

    float acc[2][8][4];
#pragma unroll
    for (int mi = 0; mi < 2; mi++)
#pragma unroll
        for (int ni = 0; ni < 8; ni++)
#pragma unroll
            for (int j = 0; j < 4; j++) acc[mi][ni][j] = 0.f;

#pragma unroll
    for (int s = 0; s < NSTAGE - 1; s++) { issue(s); CP_COMMIT(); }

#pragma unroll 1
    for (int ks = 0; ks < NKS; ks++) {
        CP_WAIT2();
        __syncthreads();
        if (ks + NSTAGE - 1 < NKS) issue(ks + NSTAGE - 1);
        CP_COMMIT();

        const uint32_t slot = (uint32_t)(ks & (NSTAGE - 1)) * STG_BYTES;
        const uint32_t* asb = (const uint32_t*)(smem + slot + A_OFF);
        const uint32_t* bsb = (const uint32_t*)(smem + slot + B_OFF);

#pragma unroll
        for (int kp = 0; kp < 2; kp++) {
            uint32_t afr[2][4];
#pragma unroll
            for (int mi = 0; mi < 2; mi++) {
                int m = wm * 32 + mi * 16 + r4;
                uint32_t a0 = asb[m * LDS_STRIDE + kp * 8 + c4];
                uint32_t a1 = asb[(m + 8) * LDS_STRIDE + kp * 8 + c4];
                uint32_t a2 = asb[m * LDS_STRIDE + kp * 8 + c4 + 4];
                uint32_t a3 = asb[(m + 8) * LDS_STRIDE + kp * 8 + c4 + 4];
                afr[mi][0] = tf32_rna(__uint_as_float(a0));
                afr[mi][1] = tf32_rna(__uint_as_float(a1));
                afr[mi][2] = tf32_rna(__uint_as_float(a2));
                afr[mi][3] = tf32_rna(__uint_as_float(a3));
            }
            uint32_t bfr[8][2];
#pragma unroll
            for (int ni = 0; ni < 8; ni++) {
                int n = wn * 64 + ni * 8 + r4;
                bfr[ni][0] = bsb[n * LDS_STRIDE + kp * 8 + c4];
                bfr[ni][1] = bsb[n * LDS_STRIDE + kp * 8 + c4 + 4];
            }
#pragma unroll
            for (int mi = 0; mi < 2; mi++)
#pragma unroll
                for (int ni = 0; ni < 8; ni++)
                    mma_tf32(acc[mi][ni], afr[mi], bfr[ni]);
        }
    }

    // ---- fused attn scalars (fp32 accumulators) ----
    float avs[8][2], avd[8][2];
#pragma unroll
    for (int ni = 0; ni < 8; ni++) {
        int gn = head * 64 + ni * 8 + c4 * 2;
        avs[ni][0] = __ldg(&att_src[gn]);
        avs[ni][1] = __ldg(&att_src[gn + 1]);
        avd[ni][0] = __ldg(&att_dst[gn]);
        avd[ni][1] = __ldg(&att_dst[gn + 1]);
    }
#pragma unroll
    for (int mi = 0; mi < 2; mi++) {
        float ps0 = 0.f, ps1 = 0.f, pd0 = 0.f, pd1 = 0.f;
#pragma unroll
        for (int ni = 0; ni < 8; ni++) {
            ps0 += acc[mi][ni][0] * avs[ni][0] + acc[mi][ni][1] * avs[ni][1];
            ps1 += acc[mi][ni][2] * avs[ni][0] + acc[mi][ni][3] * avs[ni][1];
            pd0 += acc[mi][ni][0] * avd[ni][0] + acc[mi][ni][1] * avd[ni][1];
            pd1 += acc[mi][ni][2] * avd[ni][0] + acc[mi][ni][3] * avd[ni][1];
        }
#pragma unroll
        for (int o = 1; o <= 2; o <<= 1) {
            ps0 += __shfl_xor_sync(0xffffffffu, ps0, o);
            ps1 += __shfl_xor_sync(0xffffffffu, ps1, o);
            pd0 += __shfl_xor_sync(0xffffffffu, pd0, o);
            pd1 += __shfl_xor_sync(0xffffffffu, pd1, o);
        }
        if (c4 == 0) {
            int gmA = m0 + wm * 32 + mi * 16 + r4;
            int gmB = gmA + 8;
            if (gmA < NN) { g_asrc[gmA * HH + head] = ps0; g_adst[gmA * HH + head] = pd0; }
            if (gmB < NN) { g_asrc[gmB * HH + head] = ps1; g_adst[gmB * HH + head] = pd1; }
        }
    }

    // ---- write h as fp16 (only consumer is the fp16 gather) ----
#pragma unroll
    for (int mi = 0; mi < 2; mi++) {
#pragma unroll
        for (int ni = 0; ni < 8; ni++) {
            int gm = m0 + wm * 32 + mi * 16 + r4;
            int gn = n0 + wn * 64 + ni * 8 + (c4 << 1);
            if (gm < NN)
                *(__half2*)&g_h16[(size_t)gm * HC + gn] =
                    __float22half2_rn(make_float2(acc[mi][ni][0], acc[mi][ni][1]));
            if (gm + 8 < NN)
                *(__half2*)&g_h16[(size_t)(gm + 8) * HC + gn] =
                    __float22half2_rn(make_float2(acc[mi][ni][2], acc[mi][ni][3]));
        }
    }
}

// ---------------- 3) CSR build ----------------
__global__ void deg_init_kernel() {
    int i = blockIdx.x * blockDim.x + threadIdx.x;
    if (i < NN) g_deg[i] = 1;
}

__global__ void deg_count_kernel(const int* __restrict__ ei) {
    int e = blockIdx.x * blockDim.x + threadIdx.x;
    if (e < EE) atomicAdd(&g_deg[ei[EE + e]], 1);
}

__global__ __launch_bounds__(1024) void scan_kernel() {
    __shared__ int wsum[32];
    __shared__ int s_carry;
    __shared__ int s_total;
    const int tid = threadIdx.x, lane = tid & 31, wid = tid >> 5;
    if (tid == 0) s_carry = 0;
    __syncthreads();

    for (int base = 0; base < NN; base += 1024) {
        int i = base + tid;
        int v = (i < NN) ? g_deg[i] : 0;
        int x = v;
#pragma unroll
        for (int o = 1; o < 32; o <<= 1) {
            int y = __shfl_up_sync(0xffffffffu, x, o);
            if (lane >= o) x += y;
        }
        if (lane == 31) wsum[wid] = x;
        __syncthreads();
        if (wid == 0) {
            int w = wsum[lane];
            int xs = w;
#pragma unroll
            for (int o = 1; o < 32; o <<= 1) {
                int y = __shfl_up_sync(0xffffffffu, xs, o);
                if (lane >= o) xs += y;
            }
            wsum[lane] = xs - w;
            if (lane == 31) s_total = xs;
        }
        __syncthreads();
        int incl = x + wsum[wid];
        int off  = s_carry + incl - v;
        if (i < NN) {
            g_off[i]    = off;
            g_srcid[off] = i;
            g_cur[i]    = off + 1;
        }
        __syncthreads();
        if (tid == 0) s_carry += s_total;
        __syncthreads();
    }
    if (tid == 0) g_off[NN] = s_carry;
}

__global__ void scatter_kernel(const int* __restrict__ ei) {
    int e = blockIdx.x * blockDim.x + threadIdx.x;
    if (e < EE) {
        int d = ei[EE + e];
        int p = atomicAdd(&g_cur[d], 1);
        g_srcid[p] = ei[e];
    }
}

// ---------------- 4a) softmax: per-edge exp + per-node denominators ----------------
__device__ __forceinline__ float lrelu(float x) { return x >= 0.f ? x : NEG_SLOPE * x; }

__global__ __launch_bounds__(256) void softmax_kernel() {
    int warp = (blockIdx.x * 256 + threadIdx.x) >> 5;
    int lane = threadIdx.x & 31;
    if (warp >= NN) return;
    const int node = warp;
    const int beg = g_off[node], end = g_off[node + 1];

    float4 ad = *(const float4*)(g_adst + node * HH);

    float s0 = 0.f, s1 = 0.f, s2 = 0.f, s3 = 0.f;
    for (int i = beg + lane; i < end; i += 32) {
        int s = __ldg(&g_srcid[i]);
        float4 a = *(const float4*)(g_asrc + s * HH);
        float e0 = __expf(lrelu(a.x + ad.x));
        float e1 = __expf(lrelu(a.y + ad.y));
        float e2 = __expf(lrelu(a.z + ad.z));
        float e3 = __expf(lrelu(a.w + ad.w));
        *(float4*)(g_expe + (size_t)i * HH) = make_float4(e0, e1, e2, e3);
        s0 += e0; s1 += e1; s2 += e2; s3 += e3;
    }
#pragma unroll
    for (int o = 16; o > 0; o >>= 1) {
        s0 += __shfl_xor_sync(0xffffffffu, s0, o);
        s1 += __shfl_xor_sync(0xffffffffu, s1, o);
        s2 += __shfl_xor_sync(0xffffffffu, s2, o);
        s3 += __shfl_xor_sync(0xffffffffu, s3, o);
    }
    if (lane == 0) {
        *(float4*)(g_inv + node * HH) =
            make_float4(1.f / (s0 + 1e-16f), 1.f / (s1 + 1e-16f),
                        1.f / (s2 + 1e-16f), 1.f / (s3 + 1e-16f));
    }
}

// ---------------- 4b) weighted aggregation (fp16 gather) + epilogue ----------------
__global__ __launch_bounds__(256) void agg_kernel(const float* __restrict__ bias,
                                                  const float* __restrict__ prelu_a,
                                                  float* __restrict__ out) {
    int warp = (blockIdx.x * 256 + threadIdx.x) >> 5;
    int lane = threadIdx.x & 31;
    if (warp >= NN) return;
    const int node = warp;
    const int beg = g_off[node], end = g_off[node + 1];
    const int head = lane >> 3;

    float4 inv4 = *(const float4*)(g_inv + node * HH);
    float invh = (head == 0) ? inv4.x : (head == 1) ? inv4.y : (head == 2) ? inv4.z : inv4.w;

    float acc[8];
#pragma unroll
    for (int j = 0; j < 8; j++) acc[j] = 0.f;

    const uint4* h4 = (const uint4*)g_h16;   // 8 halves per uint4; row = 32 uint4

    int i = beg;
    for (; i + 2 <= end; i += 2) {
        int sA = __ldg(&g_srcid[i]);
        int sB = __ldg(&g_srcid[i + 1]);
        float4 eA = *(const float4*)(g_expe + (size_t)i * HH);
        float4 eB = *(const float4*)(g_expe + (size_t)(i + 1) * HH);
        uint4 hA = h4[(size_t)sA * 32 + lane];
        uint4 hB = h4[(size_t)sB * 32 + lane];
        float aA = ((head == 0) ? eA.x : (head == 1) ? eA.y : (head == 2) ? eA.z : eA.w) * invh;
        float aB = ((head == 0) ? eB.x : (head == 1) ? eB.y : (head == 2) ? eB.z : eB.w) * invh;

        float2 p;
        p = __half22float2(*(__half2*)&hA.x); acc[0] = fmaf(aA, p.x, acc[0]); acc[1] = fmaf(aA, p.y, acc[1]);
        p = __half22float2(*(__half2*)&hA.y); acc[2] = fmaf(aA, p.x, acc[2]); acc[3] = fmaf(aA, p.y, acc[3]);
        p = __half22float2(*(__half2*)&hA.z); acc[4] = fmaf(aA, p.x, acc[4]); acc[5] = fmaf(aA, p.y, acc[5]);
        p = __half22float2(*(__half2*)&hA.w); acc[6] = fmaf(aA, p.x, acc[6]); acc[7] = fmaf(aA, p.y, acc[7]);
        p = __half22float2(*(__half2*)&hB.x); acc[0] = fmaf(aB, p.x, acc[0]); acc[1] = fmaf(aB, p.y, acc[1]);
        p = __half22float2(*(__half2*)&hB.y); acc[2] = fmaf(aB, p.x, acc[2]); acc[3] = fmaf(aB, p.y, acc[3]);
        p = __half22float2(*(__half2*)&hB.z); acc[4] = fmaf(aB, p.x, acc[4]); acc[5] = fmaf(aB, p.y, acc[5]);
        p = __half22float2(*(__half2*)&hB.w); acc[6] = fmaf(aB, p.x, acc[6]); acc[7] = fmaf(aB, p.y, acc[7]);
    }
    for (; i < end; i++) {
        int s = __ldg(&g_srcid[i]);
        float4 e4 = *(const float4*)(g_expe + (size_t)i * HH);
        uint4 hv = h4[(size_t)s * 32 + lane];
        float a = ((head == 0) ? e4.x : (head == 1) ? e4.y : (head == 2) ? e4.z : e4.w) * invh;
        float2 p;
        p = __half22float2(*(__half2*)&hv.x); acc[0] = fmaf(a, p.x, acc[0]); acc[1] = fmaf(a, p.y, acc[1]);
        p = __half22float2(*(__half2*)&hv.y); acc[2] = fmaf(a, p.x, acc[2]); acc[3] = fmaf(a, p.y, acc[3]);
        p = __half22float2(*(__half2*)&hv.z); acc[4] = fmaf(a, p.x, acc[4]); acc[5] = fmaf(a, p.y, acc[5]);
        p = __half22float2(*(__half2*)&hv.w); acc[6] = fmaf(a, p.x, acc[6]); acc[7] = fmaf(a, p.y, acc[7]);
    }

    const float4* b4 = (const float4*)bias;
    float4 b0 = b4[lane * 2], b1 = b4[lane * 2 + 1];
    float pa = prelu_a[0];

    float o0 = acc[0] + b0.x; o0 = o0 >= 0.f ? o0 : pa * o0;
    float o1 = acc[1] + b0.y; o1 = o1 >= 0.f ? o1 : pa * o1;
    float o2 = acc[2] + b0.z; o2 = o2 >= 0.f ? o2 : pa * o2;
    float o3 = acc[3] + b0.w; o3 = o3 >= 0.f ? o3 : pa * o3;
    float o4 = acc[4] + b1.x; o4 = o4 >= 0.f ? o4 : pa * o4;
    float o5 = acc[5] + b1.y; o5 = o5 >= 0.f ? o5 : pa * o5;
    float o6 = acc[6] + b1.z; o6 = o6 >= 0.f ? o6 : pa * o6;
    float o7 = acc[7] + b1.w; o7 = o7 >= 0.f ? o7 : pa * o7;

    float4* out4 = (float4*)out;
    out4[node * (HC / 4) + lane * 2]     = make_float4(o0, o1, o2, o3);
    out4[node * (HC / 4) + lane * 2 + 1] = make_float4(o4, o5, o6, o7);
}

// ---------------- launch ----------------
extern "C" void kernel_launch(void* const* d_in, const int* in_sizes, int n_in,
                              void* d_out, int out_size) {
    const float* x       = (const float*)d_in[0];
    const int*   ei      = (const int*)d_in[1];
    const float* W       = (const float*)d_in[2];
    const float* att_src = (const float*)d_in[3];
    const float* att_dst = (const float*)d_in[4];
    const float* bias    = (const float*)d_in[5];
    const float* prelu_a = (const float*)d_in[6];
    float* out = (float*)d_out;

    static cudaStream_t s2;
    static cudaEvent_t evf, evj;
    static bool init_done = false;
    if (!init_done) {
        cudaStreamCreateWithFlags(&s2, cudaStreamNonBlocking);
        cudaEventCreateWithFlags(&evf, cudaEventDisableTiming);
        cudaEventCreateWithFlags(&evj, cudaEventDisableTiming);
        cudaFuncSetAttribute(mma_gemm_kernel, cudaFuncAttributeMaxDynamicSharedMemorySize, GEMM_SMEM);
        init_done = true;
    }

    // fork: CSR build on side stream, overlapped with GEMM
    cudaEventRecord(evf, 0);
    cudaStreamWaitEvent(s2, evf, 0);
    deg_init_kernel<<<(NN + 255) / 256, 256, 0, s2>>>();
    deg_count_kernel<<<(EE + 255) / 256, 256, 0, s2>>>(ei);
    scan_kernel<<<1, 1024, 0, s2>>>();
    scatter_kernel<<<(EE + 255) / 256, 256, 0, s2>>>(ei);
    cudaEventRecord(evj, s2);

    // main stream: projection + fused attn scalars
    wt_kernel<<<(KIN * HC + 255) / 256, 256>>>(W);
    dim3 ggrid(2, (NN + 127) / 128);
    mma_gemm_kernel<<<ggrid, 256, GEMM_SMEM>>>(x, att_src, att_dst);

    // join, then softmax + aggregate
    cudaStreamWaitEvent(0, evj, 0);
    softmax_kernel<<<(NN * 32 + 255) / 256, 256>>>();
    agg_kernel<<<(NN * 32 + 255) / 256, 256>>>(bias, prelu_a, out);
}